// round 16
// baseline (speedup 1.0000x reference)
#include <cuda_runtime.h>
#include <cuda_fp16.h>
#include <math.h>

// Problem constants
#define BB 4
#define SS 1024
#define EE 1024
#define HH 16
#define DKK 64
#define PER (BB * HH * SS * DKK)
#define NEGV (-10000.0f)

// ---------------------------------------------------------------------------
// Scratch: fp16 hi/lo. A-sides get hi+lo; B-sides hi only.
// ---------------------------------------------------------------------------
__device__ unsigned g_xh[4096 * 512],  g_xl[4096 * 512];    // x hi/lo (A side)
__device__ unsigned g_qwh[3072 * 512];                      // qkv_w hi (B side)
__device__ unsigned g_owh[1024 * 512];                      // out_w hi (B side)
__device__ unsigned g_cth[4096 * 512], g_ctl[4096 * 512];   // ctx hi/lo (A side)
__device__ __half g_qh[3 * PER], g_ql[3 * PER];             // q|k (hi; lo for q)
__device__ __half g_vt[BB * HH * DKK * SS];                 // V^T [b,h,d,s] hi
__device__ float g_m[BB * HH * SS];                         // row max
__device__ float g_linv[BB * HH * SS];                      // 1/row denom

// ---------------------------------------------------------------------------
// helpers
// ---------------------------------------------------------------------------
__device__ __forceinline__ void mma_f16(float* d, const unsigned* a,
                                        unsigned b0, unsigned b1)
{
    asm("mma.sync.aligned.m16n8k16.row.col.f32.f16.f16.f32 "
        "{%0,%1,%2,%3}, {%4,%5,%6,%7}, {%8,%9}, {%0,%1,%2,%3};"
        : "+f"(d[0]), "+f"(d[1]), "+f"(d[2]), "+f"(d[3])
        : "r"(a[0]), "r"(a[1]), "r"(a[2]), "r"(a[3]), "r"(b0), "r"(b1));
}

__device__ __forceinline__ void ldsm4(unsigned* rg, unsigned addr)
{
    asm volatile("ldmatrix.sync.aligned.m8n8.x4.shared.b16 {%0,%1,%2,%3}, [%4];"
                 : "=r"(rg[0]), "=r"(rg[1]), "=r"(rg[2]), "=r"(rg[3])
                 : "r"(addr));
}

__device__ __forceinline__ unsigned pack_hi(float x, float y,
                                            float& rx, float& ry)
{
    __half hx = __float2half_rn(x), hy = __float2half_rn(y);
    rx = x - __half2float(hx);
    ry = y - __half2float(hy);
    __half2 t = __halves2half2(hx, hy);
    unsigned u; *(__half2*)&u = t; return u;
}
__device__ __forceinline__ unsigned pack_lo(float rx, float ry)
{
    __half2 t = __floats2half2_rn(rx, ry);
    unsigned u; *(__half2*)&u = t; return u;
}

__device__ __forceinline__ void cpa16(unsigned dst, const void* src)
{
    asm volatile("cp.async.cg.shared.global [%0], [%1], 16;"
                 :: "r"(dst), "l"(src));
}
__device__ __forceinline__ void cpa_commit()
{
    asm volatile("cp.async.commit_group;");
}
__device__ __forceinline__ void cpa_wait0()
{
    asm volatile("cp.async.wait_group 0;");
}

// ---------------------------------------------------------------------------
// Prep (single launch): fp32 -> fp16 hi(/lo for x).
// ---------------------------------------------------------------------------
__global__ void cvt_all_kernel(const float* __restrict__ x,
                               const float* __restrict__ qw,
                               const float* __restrict__ ow)
{
    const int bid = blockIdx.x;
    const float* src;
    unsigned *dh, *dl = nullptr;
    int i0;
    if (bid < 4096)      { src = x;  dh = g_xh;  dl = g_xl; i0 = bid; }
    else if (bid < 7168) { src = qw; dh = g_qwh; i0 = bid - 4096; }
    else                 { src = ow; dh = g_owh; i0 = bid - 7168; }

    const int i = i0 * 256 + threadIdx.x;
    float4 v = ((const float4*)src)[i];
    float rx, ry, rz, rw;
    unsigned h0 = pack_hi(v.x, v.y, rx, ry);
    unsigned h1 = pack_hi(v.z, v.w, rz, rw);
    dh[2 * i] = h0; dh[2 * i + 1] = h1;
    if (dl) {
        dl[2 * i]     = pack_lo(rx, ry);
        dl[2 * i + 1] = pack_lo(rz, rw);
    }
}

// ---------------------------------------------------------------------------
// GEMM: 128x128 tile, 256 threads, cp.async double-buffered, ldmatrix.
// A split (hi+lo), W hi-only. MMAs reordered: all hi-terms (4 accs) before
// lo-terms -> accumulator RAW gap 3 instead of 0. Same per-acc add order.
// MODE 0: A=x, W=qkv_w -> scatter Q (hi+lo), K (hi), V^T (hi), pad zeroed.
//         Fully padded M-tiles skip the main loop entirely.
// MODE 1: A=ctx, W=out_w -> fp32 out
// ---------------------------------------------------------------------------
#define KW 20

template <int MODE>
__global__ __launch_bounds__(256, 2) void gemm_f16_kernel(
    const float* __restrict__ bias, const unsigned int* __restrict__ kpm,
    float* __restrict__ out)
{
    extern __shared__ unsigned dynsm[];
    const unsigned *Ah, *Al, *Wh;
    if (MODE == 0) { Ah = g_xh;  Al = g_xl;  Wh = g_qwh; }
    else           { Ah = g_cth; Al = g_ctl; Wh = g_owh; }

    const int tid = threadIdx.x, lane = tid & 31, warp = tid >> 5;
    const int wm = warp >> 1, wn = warp & 1;
    const int m0 = blockIdx.y * 128, n0 = blockIdx.x * 128;
    const int r = lane >> 2, cc = lane & 3;
    const int lrow16 = lane & 15;
    const int lkoff4 = (lane >> 4) * 4;

    const unsigned sbase = (unsigned)__cvta_generic_to_shared(dynsm);

    const int c0 = tid, c1 = tid + 256;
    const int row0 = c0 >> 2, off0 = (c0 & 3) * 4;
    const int row1 = c1 >> 2, off1 = (c1 & 3) * 4;
    const unsigned so0 = (unsigned)(row0 * KW + off0) * 4u;
    const unsigned so1 = (unsigned)(row1 * KW + off1) * 4u;
    const size_t ga0 = (size_t)(m0 + row0) * 512 + off0;
    const size_t ga1 = (size_t)(m0 + row1) * 512 + off1;
    const size_t gb0 = (size_t)(n0 + row0) * 512 + off0;
    const size_t gb1 = (size_t)(n0 + row1) * 512 + off1;

    float acc[2][8][4];
#pragma unroll
    for (int i = 0; i < 2; i++)
#pragma unroll
        for (int j = 0; j < 8; j++)
#pragma unroll
            for (int c = 0; c < 4; c++) acc[i][j][c] = 0.0f;

    // Fully padded M-tile? (padding is a suffix per batch, so first row decides)
    bool skiptile = false;
    if (MODE == 0)
        skiptile = (kpm[(m0 >> 10) * 1024 + (m0 & 1023)] != 0u);

#define ISSUE(kt, st) do {                                                  \
    const int kk_ = (kt) * 16;                                              \
    const unsigned sb_ = sbase + (unsigned)(st) * 30720u;                   \
    cpa16(sb_ +      0u + so0, Ah + ga0 + kk_);                             \
    cpa16(sb_ +      0u + so1, Ah + ga1 + kk_);                             \
    cpa16(sb_ + 10240u + so0, Al + ga0 + kk_);                              \
    cpa16(sb_ + 10240u + so1, Al + ga1 + kk_);                              \
    cpa16(sb_ + 20480u + so0, Wh + gb0 + kk_);                              \
    cpa16(sb_ + 20480u + so1, Wh + gb1 + kk_);                              \
    cpa_commit(); } while (0)

    if (!skiptile) {
        ISSUE(0, 0);

        for (int kt = 0; kt < 32; kt++) {
            cpa_wait0();
            __syncthreads();
            if (kt < 31) ISSUE(kt + 1, (kt + 1) & 1);

            const unsigned stoff = sbase + (unsigned)(kt & 1) * 30720u;

#pragma unroll
            for (int half = 0; half < 2; half++) {
                const int kwb = half * 8;
                unsigned ah[2][4], al[2][4];
#pragma unroll
                for (int mi = 0; mi < 2; mi++) {
                    const unsigned aoffb = (unsigned)
                        ((wm * 32 + mi * 16 + lrow16) * KW + kwb + lkoff4) * 4u;
                    ldsm4(ah[mi], stoff + aoffb);
                    ldsm4(al[mi], stoff + 10240u + aoffb);
                }
#pragma unroll
                for (int p = 0; p < 4; p++) {
                    const unsigned boff = (unsigned)
                        ((wn * 64 + p * 16 + lrow16) * KW + kwb + lkoff4) * 4u;
                    unsigned bh[4];
                    ldsm4(bh, stoff + 20480u + boff);
                    // hi terms across 4 accumulators, then lo terms (RAW gap 3)
                    mma_f16(acc[0][2 * p],     ah[0], bh[0], bh[2]);
                    mma_f16(acc[1][2 * p],     ah[1], bh[0], bh[2]);
                    mma_f16(acc[0][2 * p + 1], ah[0], bh[1], bh[3]);
                    mma_f16(acc[1][2 * p + 1], ah[1], bh[1], bh[3]);
                    mma_f16(acc[0][2 * p],     al[0], bh[0], bh[2]);
                    mma_f16(acc[1][2 * p],     al[1], bh[0], bh[2]);
                    mma_f16(acc[0][2 * p + 1], al[0], bh[1], bh[3]);
                    mma_f16(acc[1][2 * p + 1], al[1], bh[1], bh[3]);
                }
            }
            __syncthreads();
        }
    }
#undef ISSUE

#pragma unroll
    for (int mi = 0; mi < 2; mi++) {
        const int mbase = m0 + wm * 32 + mi * 16 + r;
#pragma unroll
        for (int rr = 0; rr < 2; rr++) {
            const int m = mbase + rr * 8;
            if (MODE == 0) {
                const int b = m >> 10, s = m & 1023;
                const bool pad = (kpm[b * 1024 + s] != 0u);
#pragma unroll
                for (int ni = 0; ni < 8; ni++) {
                    const int c = n0 + wn * 64 + ni * 8 + cc * 2;
                    const float v0 = pad ? 0.0f : (acc[mi][ni][rr * 2]     + bias[c]);
                    const float v1 = pad ? 0.0f : (acc[mi][ni][rr * 2 + 1] + bias[c + 1]);
                    const int which = c >> 10;
                    const int e = c & 1023;
                    const int hh = e >> 6, d = e & 63;
                    __half h0 = __float2half_rn(v0), h1 = __float2half_rn(v1);
                    if (which == 0) {
                        const size_t idx = ((size_t)(b * HH + hh) * SS + s) * DKK + d;
                        __half l0 = __float2half_rn(v0 - __half2float(h0));
                        __half l1 = __float2half_rn(v1 - __half2float(h1));
                        *(__half2*)&g_qh[idx] = __halves2half2(h0, h1);
                        *(__half2*)&g_ql[idx] = __halves2half2(l0, l1);
                    } else if (which == 1) {
                        const size_t idx = (size_t)PER
                                         + ((size_t)(b * HH + hh) * SS + s) * DKK + d;
                        *(__half2*)&g_qh[idx] = __halves2half2(h0, h1);
                    } else {
                        __half* vt = g_vt + (size_t)(b * HH + hh) * DKK * SS;
                        vt[(size_t)d * SS + s]       = h0;
                        vt[(size_t)(d + 1) * SS + s] = h1;
                    }
                }
            } else {
#pragma unroll
                for (int ni = 0; ni < 8; ni++) {
                    const int n = n0 + wn * 64 + ni * 8 + cc * 2;
                    out[(size_t)m * 1024 + n]     = acc[mi][ni][rr * 2]     + bias[n];
                    out[(size_t)m * 1024 + n + 1] = acc[mi][ni][rr * 2 + 1] + bias[n + 1];
                }
            }
        }
    }
}

// ---------------------------------------------------------------------------
// Attention Pass A: STATS ONLY. Skips causal-masked AND fully-padded key
// tiles (exact: their softmax contribution underflows to +0).
// ---------------------------------------------------------------------------
#define QS 36

__global__ __launch_bounds__(256) void attn_score_kernel(
    const unsigned int* __restrict__ kpm)
{
    extern __shared__ unsigned sm[];
    unsigned* sQh = sm;
    unsigned* sQl = sQh + 128 * QS;
    unsigned* sKh = sQl + 128 * QS;
    unsigned* sKp = sKh + 128 * QS;

    const int b = blockIdx.z, h = blockIdx.y, q0 = blockIdx.x * 128;
    const int tid = threadIdx.x, lane = tid & 31, w = tid >> 5;
    const int r = lane >> 2, cc = lane & 3;
    const int lrow16 = lane & 15;
    const int lkoff4 = (lane >> 4) * 4;

    const unsigned sKh_u = (unsigned)__cvta_generic_to_shared(sKh);

    const unsigned* qhw = (const unsigned*)g_qh;
    const unsigned* qlw = (const unsigned*)g_ql;
    const size_t qbase = ((size_t)(b * HH + h) * SS + q0) * 32;
    const size_t kbase = (size_t)PER / 2 + ((size_t)(b * HH + h) * SS) * 32;

    for (int i = tid; i < 1024; i += 256) {
        const int row = i >> 3, off = (i & 7) * 4;
        *(uint4*)&sQh[row * QS + off] = *(const uint4*)(qhw + qbase + row * 32 + off);
        *(uint4*)&sQl[row * QS + off] = *(const uint4*)(qlw + qbase + row * 32 + off);
    }
    __syncthreads();

    const int qr = w * 16 + r;
    unsigned aQh[4][4], aQl[4][4];
#pragma unroll
    for (int ks = 0; ks < 4; ks++) {
        const int bw = ks * 8 + cc;
        aQh[ks][0] = sQh[qr * QS + bw];
        aQh[ks][1] = sQh[(qr + 8) * QS + bw];
        aQh[ks][2] = sQh[qr * QS + bw + 4];
        aQh[ks][3] = sQh[(qr + 8) * QS + bw + 4];
        aQl[ks][0] = sQl[qr * QS + bw];
        aQl[ks][1] = sQl[(qr + 8) * QS + bw];
        aQl[ks][2] = sQl[qr * QS + bw + 4];
        aQl[ks][3] = sQl[(qr + 8) * QS + bw + 4];
    }

    const int row0 = q0 + qr, row1 = row0 + 8;

    float m_run[2] = {-1e30f, -1e30f};
    float l_run[2] = {0.0f, 0.0f};

    // first fully padded key tile (padding is a suffix; len >= 512 -> >= 4)
    int ktpad = 8;
#pragma unroll
    for (int t = 7; t >= 0; t--)
        if (kpm[b * 1024 + t * 128] != 0u) ktpad = t;

    const int ntend = min(blockIdx.x, (unsigned)(ktpad - 1));
    for (int nt = 0; nt <= ntend; nt++) {
        __syncthreads();
        for (int i = tid; i < 1024; i += 256) {
            const int row = i >> 3, off = (i & 7) * 4;
            const size_t g = kbase + (size_t)(nt * 128 + row) * 32 + off;
            *(uint4*)&sKh[row * QS + off] = *(const uint4*)(qhw + g);
        }
        if (tid < 128) sKp[tid] = kpm[b * 1024 + nt * 128 + tid];
        __syncthreads();

        float acc[16][4];
#pragma unroll
        for (int ni = 0; ni < 16; ni++)
#pragma unroll
            for (int c = 0; c < 4; c++) acc[ni][c] = 0.0f;

#pragma unroll
        for (int ks = 0; ks < 4; ks++) {
#pragma unroll
            for (int pp = 0; pp < 4; pp++) {
                const unsigned koffA = (unsigned)
                    (((2 * pp) * 16 + lrow16) * QS + ks * 8 + lkoff4) * 4u;
                const unsigned koffB = (unsigned)
                    (((2 * pp + 1) * 16 + lrow16) * QS + ks * 8 + lkoff4) * 4u;
                unsigned ba[4], bb[4];
                ldsm4(ba, sKh_u + koffA);
                ldsm4(bb, sKh_u + koffB);
                mma_f16(acc[4 * pp],     aQh[ks], ba[0], ba[2]);
                mma_f16(acc[4 * pp + 1], aQh[ks], ba[1], ba[3]);
                mma_f16(acc[4 * pp + 2], aQh[ks], bb[0], bb[2]);
                mma_f16(acc[4 * pp + 3], aQh[ks], bb[1], bb[3]);
                mma_f16(acc[4 * pp],     aQl[ks], ba[0], ba[2]);
                mma_f16(acc[4 * pp + 1], aQl[ks], ba[1], ba[3]);
                mma_f16(acc[4 * pp + 2], aQl[ks], bb[0], bb[2]);
                mma_f16(acc[4 * pp + 3], aQl[ks], bb[1], bb[3]);
            }
        }

#pragma unroll
        for (int ni = 0; ni < 16; ni++) {
            const int colb = ni * 8 + cc * 2;
            const int col = nt * 128 + colb;
#pragma unroll
            for (int e = 0; e < 2; e++) {
                const bool pad = (sKp[colb + e] != 0u);
                float s0 = acc[ni][e] * 0.125f;
                if (col + e > row0) s0 += NEGV;
                if (pad) s0 = NEGV;
                acc[ni][e] = s0;
                float s1 = acc[ni][2 + e] * 0.125f;
                if (col + e > row1) s1 += NEGV;
                if (pad) s1 = NEGV;
                acc[ni][2 + e] = s1;
            }
        }

        float tm0 = -1e30f, tm1 = -1e30f;
#pragma unroll
        for (int ni = 0; ni < 16; ni++) {
            tm0 = fmaxf(tm0, fmaxf(acc[ni][0], acc[ni][1]));
            tm1 = fmaxf(tm1, fmaxf(acc[ni][2], acc[ni][3]));
        }
        tm0 = fmaxf(tm0, __shfl_xor_sync(0xFFFFFFFFu, tm0, 1));
        tm0 = fmaxf(tm0, __shfl_xor_sync(0xFFFFFFFFu, tm0, 2));
        tm1 = fmaxf(tm1, __shfl_xor_sync(0xFFFFFFFFu, tm1, 1));
        tm1 = fmaxf(tm1, __shfl_xor_sync(0xFFFFFFFFu, tm1, 2));
        const float nm0 = fmaxf(m_run[0], tm0);
        const float nm1 = fmaxf(m_run[1], tm1);
        float s0 = 0.0f, s1 = 0.0f;
#pragma unroll
        for (int ni = 0; ni < 16; ni++) {
            s0 += __expf(acc[ni][0] - nm0) + __expf(acc[ni][1] - nm0);
            s1 += __expf(acc[ni][2] - nm1) + __expf(acc[ni][3] - nm1);
        }
        s0 += __shfl_xor_sync(0xFFFFFFFFu, s0, 1);
        s0 += __shfl_xor_sync(0xFFFFFFFFu, s0, 2);
        s1 += __shfl_xor_sync(0xFFFFFFFFu, s1, 1);
        s1 += __shfl_xor_sync(0xFFFFFFFFu, s1, 2);
        l_run[0] = l_run[0] * __expf(m_run[0] - nm0) + s0;
        l_run[1] = l_run[1] * __expf(m_run[1] - nm1) + s1;
        m_run[0] = nm0; m_run[1] = nm1;
    }

    if (cc == 0) {
        const int sb_ = (b * HH + h) * SS;
        g_m[sb_ + row0] = m_run[0];
        g_m[sb_ + row1] = m_run[1];
        g_linv[sb_ + row0] = 1.0f / l_run[0];
        g_linv[sb_ + row1] = 1.0f / l_run[1];
    }
}

// ---------------------------------------------------------------------------
// Attention Pass B: recompute scores, w = exp(s-m)/l -> single gmem write,
// register-repack w, ctx = W @ V. Skips causal + fully-padded tiles (zeroed).
// ---------------------------------------------------------------------------
#define WS 68

__global__ __launch_bounds__(256, 2) void attn_av_kernel(
    const unsigned int* __restrict__ kpm, float* __restrict__ wout)
{
    extern __shared__ unsigned sm2[];
    unsigned* bufK = sm2;
    unsigned* bufV = bufK + 128 * QS;
    unsigned* sKp  = bufV + 128 * QS;
    float*    sM   = (float*)(sKp + 128);
    float*    sLi  = sM + 128;

    const int b = blockIdx.z, h = blockIdx.y, q0 = blockIdx.x * 128;
    const int tid = threadIdx.x, lane = tid & 31, w = tid >> 5;
    const int r = lane >> 2, cc = lane & 3;
    const int lrow16 = lane & 15;
    const int lkoff4 = (lane >> 4) * 4;

    const unsigned bufK_u = (unsigned)__cvta_generic_to_shared(bufK);
    const unsigned bufV_u = (unsigned)__cvta_generic_to_shared(bufV);

    const unsigned* qhw = (const unsigned*)g_qh;
    const unsigned* qlw = (const unsigned*)g_ql;
    const size_t qbase = ((size_t)(b * HH + h) * SS + q0) * 32;
    const size_t kbase = (size_t)PER / 2 + ((size_t)(b * HH + h) * SS) * 32;
    const __half* vt = g_vt + (size_t)(b * HH + h) * DKK * SS;

    if (tid < 128) {
        const int sb_ = (b * HH + h) * SS + q0;
        sM[tid]  = g_m[sb_ + tid];
        sLi[tid] = g_linv[sb_ + tid];
    }

    for (int i = tid; i < 1024; i += 256) {
        const int row = i >> 3, off = (i & 7) * 4;
        *(uint4*)&bufK[row * QS + off] = *(const uint4*)(qhw + qbase + row * 32 + off);
        *(uint4*)&bufV[row * QS + off] = *(const uint4*)(qlw + qbase + row * 32 + off);
    }
    __syncthreads();

    const int qr = w * 16 + r;
    unsigned aQh[4][4], aQl[4][4];
#pragma unroll
    for (int ks = 0; ks < 4; ks++) {
        const int bw = ks * 8 + cc;
        aQh[ks][0] = bufK[qr * QS + bw];
        aQh[ks][1] = bufK[(qr + 8) * QS + bw];
        aQh[ks][2] = bufK[qr * QS + bw + 4];
        aQh[ks][3] = bufK[(qr + 8) * QS + bw + 4];
        aQl[ks][0] = bufV[qr * QS + bw];
        aQl[ks][1] = bufV[(qr + 8) * QS + bw];
        aQl[ks][2] = bufV[qr * QS + bw + 4];
        aQl[ks][3] = bufV[(qr + 8) * QS + bw + 4];
    }

    const int row0 = q0 + qr, row1 = row0 + 8;
    const float mm0 = sM[qr],     li0 = sLi[qr];
    const float mm1 = sM[qr + 8], li1 = sLi[qr + 8];
    float* wrow0 = wout + ((size_t)(b * HH + h) * SS + row0) * SS;
    float* wrow1 = wout + ((size_t)(b * HH + h) * SS + row1) * SS;

    float accO[8][4];
#pragma unroll
    for (int ni = 0; ni < 8; ni++)
#pragma unroll
        for (int c = 0; c < 4; c++) accO[ni][c] = 0.0f;

    int ktpad = 8;
#pragma unroll
    for (int t = 7; t >= 0; t--)
        if (kpm[b * 1024 + t * 128] != 0u) ktpad = t;

    const int ktend = min(blockIdx.x, (unsigned)(ktpad - 1));

    for (int kt = 0; kt <= ktend; kt++) {
        __syncthreads();
        for (int i = tid; i < 1024; i += 256) {
            const int row = i >> 3, off = (i & 7) * 4;
            cpa16(bufK_u + (unsigned)(row * QS + off) * 4u,
                  qhw + kbase + (size_t)(kt * 128 + row) * 32 + off);
        }
        for (int c = tid; c < 1024; c += 256) {
            const int d = c >> 4, off = c & 15;
            cpa16(bufV_u + (unsigned)(d * WS + off * 4) * 4u,
                  vt + (size_t)d * SS + kt * 128 + off * 8);
        }
        cpa_commit();
        if (tid < 128) sKp[tid] = kpm[b * 1024 + kt * 128 + tid];
        cpa_wait0();
        __syncthreads();

#pragma unroll
        for (int half = 0; half < 2; half++) {
            float acc[8][4];
#pragma unroll
            for (int ni = 0; ni < 8; ni++)
#pragma unroll
                for (int c = 0; c < 4; c++) acc[ni][c] = 0.0f;

            // score MMA for the 64-key half (paired, RAW gap 3)
#pragma unroll
            for (int ks = 0; ks < 4; ks++) {
#pragma unroll
                for (int pp = 0; pp < 2; pp++) {
                    const unsigned koffA = (unsigned)
                        (((half * 4 + 2 * pp) * 16 + lrow16) * QS + ks * 8 + lkoff4) * 4u;
                    const unsigned koffB = (unsigned)
                        (((half * 4 + 2 * pp + 1) * 16 + lrow16) * QS + ks * 8 + lkoff4) * 4u;
                    unsigned ba[4], bb[4];
                    ldsm4(ba, bufK_u + koffA);
                    ldsm4(bb, bufK_u + koffB);
                    mma_f16(acc[4 * pp],     aQh[ks], ba[0], ba[2]);
                    mma_f16(acc[4 * pp + 1], aQh[ks], ba[1], ba[3]);
                    mma_f16(acc[4 * pp + 2], aQh[ks], bb[0], bb[2]);
                    mma_f16(acc[4 * pp + 3], aQh[ks], bb[1], bb[3]);
                    mma_f16(acc[4 * pp],     aQl[ks], ba[0], ba[2]);
                    mma_f16(acc[4 * pp + 1], aQl[ks], ba[1], ba[3]);
                    mma_f16(acc[4 * pp + 2], aQl[ks], bb[0], bb[2]);
                    mma_f16(acc[4 * pp + 3], aQl[ks], bb[1], bb[3]);
                }
            }

            // epilogue + repack + PV per 16-key chunk
#pragma unroll
            for (int pi = 0; pi < 4; pi++) {
#pragma unroll
                for (int sub = 0; sub < 2; sub++) {
                    const int nl = 2 * pi + sub;
                    const int colb = (half * 8 + nl) * 8 + cc * 2;
                    const int col = kt * 128 + colb;
#pragma unroll
                    for (int e = 0; e < 2; e++) {
                        const bool pad = (sKp[colb + e] != 0u);
                        float s0 = acc[nl][e] * 0.125f;
                        if (col + e > row0) s0 += NEGV;
                        if (pad) s0 = NEGV;
                        acc[nl][e] = __expf(s0 - mm0) * li0;
                        float s1 = acc[nl][2 + e] * 0.125f;
                        if (col + e > row1) s1 += NEGV;
                        if (pad) s1 = NEGV;
                        acc[nl][2 + e] = __expf(s1 - mm1) * li1;
                    }
                    *(float2*)(wrow0 + col) = make_float2(acc[nl][0], acc[nl][1]);
                    *(float2*)(wrow1 + col) = make_float2(acc[nl][2], acc[nl][3]);
                }
                unsigned ah[4], al[4];
                float rx, ry;
                ah[0] = pack_hi(acc[2 * pi][0],     acc[2 * pi][1],     rx, ry);
                al[0] = pack_lo(rx, ry);
                ah[1] = pack_hi(acc[2 * pi][2],     acc[2 * pi][3],     rx, ry);
                al[1] = pack_lo(rx, ry);
                ah[2] = pack_hi(acc[2 * pi + 1][0], acc[2 * pi + 1][1], rx, ry);
                al[2] = pack_lo(rx, ry);
                ah[3] = pack_hi(acc[2 * pi + 1][2], acc[2 * pi + 1][3], rx, ry);
                al[3] = pack_lo(rx, ry);

                const int ksv = half * 4 + pi;
#pragma unroll
                for (int pp = 0; pp < 2; pp++) {
                    const unsigned voffA = (unsigned)
                        (((2 * pp) * 16 + lrow16) * WS + ksv * 8 + lkoff4) * 4u;
                    const unsigned voffB = (unsigned)
                        (((2 * pp + 1) * 16 + lrow16) * WS + ksv * 8 + lkoff4) * 4u;
                    unsigned ba[4], bb[4];
                    ldsm4(ba, bufV_u + voffA);
                    ldsm4(bb, bufV_u + voffB);
                    mma_f16(accO[4 * pp],     ah, ba[0], ba[2]);
                    mma_f16(accO[4 * pp + 1], ah, ba[1], ba[3]);
                    mma_f16(accO[4 * pp + 2], ah, bb[0], bb[2]);
                    mma_f16(accO[4 * pp + 3], ah, bb[1], bb[3]);
                    mma_f16(accO[4 * pp],     al, ba[0], ba[2]);
                    mma_f16(accO[4 * pp + 1], al, ba[1], ba[3]);
                    mma_f16(accO[4 * pp + 2], al, bb[0], bb[2]);
                    mma_f16(accO[4 * pp + 3], al, bb[1], bb[3]);
                }
            }
        }
    }

    // zero-fill weights for skipped tiles (causal and/or fully padded)
    {
        const float4 z4 = make_float4(0.f, 0.f, 0.f, 0.f);
        float* wbase = wout + ((size_t)(b * HH + h) * SS + q0) * SS;
        for (int kt = ktend + 1; kt < 8; kt++)
            for (int i = tid; i < 4096; i += 256) {
                const int row = i >> 5, c4 = (i & 31) * 4;
                *(float4*)(wbase + (size_t)row * SS + kt * 128 + c4) = z4;
            }
    }

    __half* cth = (__half*)g_cth;
    __half* ctl = (__half*)g_ctl;
    const size_t o0 = ((size_t)(b * SS + q0 + qr)) * EE + h * DKK;
    const size_t o1 = ((size_t)(b * SS + q0 + qr + 8)) * EE + h * DKK;
#pragma unroll
    for (int ni = 0; ni < 8; ni++) {
        const int d0 = ni * 8 + cc * 2;
        __half h0 = __float2half_rn(accO[ni][0]), h1 = __float2half_rn(accO[ni][1]);
        __half l0 = __float2half_rn(accO[ni][0] - __half2float(h0));
        __half l1 = __float2half_rn(accO[ni][1] - __half2float(h1));
        *(__half2*)(cth + o0 + d0) = __halves2half2(h0, h1);
        *(__half2*)(ctl + o0 + d0) = __halves2half2(l0, l1);
        h0 = __float2half_rn(accO[ni][2]); h1 = __float2half_rn(accO[ni][3]);
        l0 = __float2half_rn(accO[ni][2] - __half2float(h0));
        l1 = __float2half_rn(accO[ni][3] - __half2float(h1));
        *(__half2*)(cth + o1 + d0) = __halves2half2(h0, h1);
        *(__half2*)(ctl + o1 + d0) = __halves2half2(l0, l1);
    }
}

// ---------------------------------------------------------------------------
extern "C" void kernel_launch(void* const* d_in, const int* in_sizes, int n_in,
                              void* d_out, int out_size)
{
    const float*        x     = (const float*)d_in[0];
    const unsigned int* kpm   = (const unsigned int*)d_in[2];
    const float*        qkv_w = (const float*)d_in[3];
    const float*        qkv_b = (const float*)d_in[4];
    const float*        out_w = (const float*)d_in[5];
    const float*        out_b = (const float*)d_in[6];

    float* out  = (float*)d_out;
    float* wout = out + (size_t)BB * SS * EE;

    const int gemmSmem  = 2 * 3 * 2560 * 4;                        // 60 KB
    const int scoreSmem = (3 * 128 * QS + 128) * 4;                // ~54 KB
    const int avSmem    = (2 * 128 * QS + 128 + 256) * 4;          // ~38 KB
    cudaFuncSetAttribute(gemm_f16_kernel<0>,
                         cudaFuncAttributeMaxDynamicSharedMemorySize, gemmSmem);
    cudaFuncSetAttribute(gemm_f16_kernel<1>,
                         cudaFuncAttributeMaxDynamicSharedMemorySize, gemmSmem);
    cudaFuncSetAttribute(attn_score_kernel,
                         cudaFuncAttributeMaxDynamicSharedMemorySize, scoreSmem);
    cudaFuncSetAttribute(attn_av_kernel,
                         cudaFuncAttributeMaxDynamicSharedMemorySize, avSmem);

    // 0) one-time conversions (single launch)
    cvt_all_kernel<<<8192, 256>>>(x, qkv_w, out_w);

    // 1) QKV projection -> Q (hi/lo), K (hi), V^T (hi)
    gemm_f16_kernel<0><<<dim3(24, 32), 256, gemmSmem>>>(qkv_b, kpm, nullptr);

    // 2a) stats only
    attn_score_kernel<<<dim3(8, HH, BB), 256, scoreSmem>>>(kpm);

    // 2b) recompute scores + softmax weights (single write) + ctx
    attn_av_kernel<<<dim3(8, HH, BB), 256, avSmem>>>(kpm, wout);

    // 3) output projection
    gemm_f16_kernel<1><<<dim3(8, 32), 256, gemmSmem>>>(out_b, nullptr, out);
}

// round 17
// speedup vs baseline: 1.0509x; 1.0509x over previous
#include <cuda_runtime.h>
#include <cuda_fp16.h>
#include <math.h>

// Problem constants
#define BB 4
#define SS 1024
#define EE 1024
#define HH 16
#define DKK 64
#define PER (BB * HH * SS * DKK)
#define NEGV (-10000.0f)

// ---------------------------------------------------------------------------
// Scratch: fp16 hi/lo. A-sides get hi+lo; B-sides hi only.
// ---------------------------------------------------------------------------
__device__ unsigned g_xh[4096 * 512],  g_xl[4096 * 512];    // x hi/lo (A side)
__device__ unsigned g_qwh[3072 * 512];                      // qkv_w hi (B side)
__device__ unsigned g_owh[1024 * 512];                      // out_w hi (B side)
__device__ unsigned g_cth[4096 * 512], g_ctl[4096 * 512];   // ctx hi/lo (A side)
__device__ __half g_qh[3 * PER], g_ql[3 * PER];             // q|k (hi; lo for q)
__device__ __half g_vt[BB * HH * DKK * SS];                 // V^T [b,h,d,s] hi
__device__ float g_m[BB * HH * SS];                         // row max
__device__ float g_linv[BB * HH * SS];                      // 1/row denom

// ---------------------------------------------------------------------------
// helpers
// ---------------------------------------------------------------------------
__device__ __forceinline__ void mma_f16(float* d, const unsigned* a,
                                        unsigned b0, unsigned b1)
{
    asm("mma.sync.aligned.m16n8k16.row.col.f32.f16.f16.f32 "
        "{%0,%1,%2,%3}, {%4,%5,%6,%7}, {%8,%9}, {%0,%1,%2,%3};"
        : "+f"(d[0]), "+f"(d[1]), "+f"(d[2]), "+f"(d[3])
        : "r"(a[0]), "r"(a[1]), "r"(a[2]), "r"(a[3]), "r"(b0), "r"(b1));
}

__device__ __forceinline__ void ldsm4(unsigned* rg, unsigned addr)
{
    asm volatile("ldmatrix.sync.aligned.m8n8.x4.shared.b16 {%0,%1,%2,%3}, [%4];"
                 : "=r"(rg[0]), "=r"(rg[1]), "=r"(rg[2]), "=r"(rg[3])
                 : "r"(addr));
}

__device__ __forceinline__ unsigned pack_hi(float x, float y,
                                            float& rx, float& ry)
{
    __half hx = __float2half_rn(x), hy = __float2half_rn(y);
    rx = x - __half2float(hx);
    ry = y - __half2float(hy);
    __half2 t = __halves2half2(hx, hy);
    unsigned u; *(__half2*)&u = t; return u;
}
__device__ __forceinline__ unsigned pack_lo(float rx, float ry)
{
    __half2 t = __floats2half2_rn(rx, ry);
    unsigned u; *(__half2*)&u = t; return u;
}

__device__ __forceinline__ void cpa16(unsigned dst, const void* src)
{
    asm volatile("cp.async.cg.shared.global [%0], [%1], 16;"
                 :: "r"(dst), "l"(src));
}
__device__ __forceinline__ void cpa_commit()
{
    asm volatile("cp.async.commit_group;");
}
__device__ __forceinline__ void cpa_wait0()
{
    asm volatile("cp.async.wait_group 0;");
}

// ---------------------------------------------------------------------------
// Prep (single launch): fp32 -> fp16 hi(/lo for x).
// ---------------------------------------------------------------------------
__global__ void cvt_all_kernel(const float* __restrict__ x,
                               const float* __restrict__ qw,
                               const float* __restrict__ ow)
{
    const int bid = blockIdx.x;
    const float* src;
    unsigned *dh, *dl = nullptr;
    int i0;
    if (bid < 4096)      { src = x;  dh = g_xh;  dl = g_xl; i0 = bid; }
    else if (bid < 7168) { src = qw; dh = g_qwh; i0 = bid - 4096; }
    else                 { src = ow; dh = g_owh; i0 = bid - 7168; }

    const int i = i0 * 256 + threadIdx.x;
    float4 v = ((const float4*)src)[i];
    float rx, ry, rz, rw;
    unsigned h0 = pack_hi(v.x, v.y, rx, ry);
    unsigned h1 = pack_hi(v.z, v.w, rz, rw);
    dh[2 * i] = h0; dh[2 * i + 1] = h1;
    if (dl) {
        dl[2 * i]     = pack_lo(rx, ry);
        dl[2 * i + 1] = pack_lo(rz, rw);
    }
}

// ---------------------------------------------------------------------------
// GEMM: 128x256 tile, 512 threads (16 warps, warp tile 32x64),
// cp.async double-buffered, ldmatrix, reordered MMAs (RAW gap 3).
// A split (hi+lo), W hi-only.
// MODE 0: A=x, W=qkv_w -> scatter Q (hi+lo), K (hi), V^T (hi), pad zeroed.
//         Fully padded M-tiles skip the main loop.
// MODE 1: A=ctx, W=out_w -> fp32 out
// smem/stage: Ah 2560 | Al 2560 | Wh 5120 words = 40960 B; 2 stages = 80 KB
// ---------------------------------------------------------------------------
#define KW 20

template <int MODE>
__global__ __launch_bounds__(512, 1) void gemm_f16_kernel(
    const float* __restrict__ bias, const unsigned int* __restrict__ kpm,
    float* __restrict__ out)
{
    extern __shared__ unsigned dynsm[];
    const unsigned *Ah, *Al, *Wh;
    if (MODE == 0) { Ah = g_xh;  Al = g_xl;  Wh = g_qwh; }
    else           { Ah = g_cth; Al = g_ctl; Wh = g_owh; }

    const int tid = threadIdx.x, lane = tid & 31, warp = tid >> 5;
    const int wm = warp >> 2, wn = warp & 3;
    const int m0 = blockIdx.y * 128, n0 = blockIdx.x * 256;
    const int r = lane >> 2, cc = lane & 3;
    const int lrow16 = lane & 15;
    const int lkoff4 = (lane >> 4) * 4;

    const unsigned sbase = (unsigned)__cvta_generic_to_shared(dynsm);

    // loads: thread owns A-hi/A-lo chunk (row tid>>2) and two W chunks
    const int arow  = tid >> 2;
    const int aoff4 = (tid & 3) * 4;
    const unsigned soA  = (unsigned)(arow * KW + aoff4) * 4u;
    const unsigned soW1 = (unsigned)((arow + 128) * KW + aoff4) * 4u;
    const size_t gaA = (size_t)(m0 + arow) * 512 + aoff4;
    const size_t gw0 = (size_t)(n0 + arow) * 512 + aoff4;
    const size_t gw1 = (size_t)(n0 + arow + 128) * 512 + aoff4;

    float acc[2][8][4];
#pragma unroll
    for (int i = 0; i < 2; i++)
#pragma unroll
        for (int j = 0; j < 8; j++)
#pragma unroll
            for (int c = 0; c < 4; c++) acc[i][j][c] = 0.0f;

    bool skiptile = false;
    if (MODE == 0)
        skiptile = (kpm[(m0 >> 10) * 1024 + (m0 & 1023)] != 0u);

#define ISSUE(kt, st) do {                                                  \
    const int kk_ = (kt) * 16;                                              \
    const unsigned sb_ = sbase + (unsigned)(st) * 40960u;                   \
    cpa16(sb_ +      0u + soA,  Ah + gaA + kk_);                            \
    cpa16(sb_ + 10240u + soA,  Al + gaA + kk_);                             \
    cpa16(sb_ + 20480u + soA,  Wh + gw0 + kk_);                             \
    cpa16(sb_ + 20480u + soW1, Wh + gw1 + kk_);                             \
    cpa_commit(); } while (0)

    if (!skiptile) {
        ISSUE(0, 0);

        for (int kt = 0; kt < 32; kt++) {
            cpa_wait0();
            __syncthreads();
            if (kt < 31) ISSUE(kt + 1, (kt + 1) & 1);

            const unsigned stoff = sbase + (unsigned)(kt & 1) * 40960u;

#pragma unroll
            for (int half = 0; half < 2; half++) {
                const int kwb = half * 8;
                unsigned ah[2][4], al[2][4];
#pragma unroll
                for (int mi = 0; mi < 2; mi++) {
                    const unsigned aoffb = (unsigned)
                        ((wm * 32 + mi * 16 + lrow16) * KW + kwb + lkoff4) * 4u;
                    ldsm4(ah[mi], stoff + aoffb);
                    ldsm4(al[mi], stoff + 10240u + aoffb);
                }
#pragma unroll
                for (int p = 0; p < 4; p++) {
                    const unsigned boff = (unsigned)
                        ((wn * 64 + p * 16 + lrow16) * KW + kwb + lkoff4) * 4u;
                    unsigned bh[4];
                    ldsm4(bh, stoff + 20480u + boff);
                    // hi terms across 4 accumulators, then lo terms
                    mma_f16(acc[0][2 * p],     ah[0], bh[0], bh[2]);
                    mma_f16(acc[1][2 * p],     ah[1], bh[0], bh[2]);
                    mma_f16(acc[0][2 * p + 1], ah[0], bh[1], bh[3]);
                    mma_f16(acc[1][2 * p + 1], ah[1], bh[1], bh[3]);
                    mma_f16(acc[0][2 * p],     al[0], bh[0], bh[2]);
                    mma_f16(acc[1][2 * p],     al[1], bh[0], bh[2]);
                    mma_f16(acc[0][2 * p + 1], al[0], bh[1], bh[3]);
                    mma_f16(acc[1][2 * p + 1], al[1], bh[1], bh[3]);
                }
            }
            __syncthreads();
        }
    }
#undef ISSUE

#pragma unroll
    for (int mi = 0; mi < 2; mi++) {
        const int mbase = m0 + wm * 32 + mi * 16 + r;
#pragma unroll
        for (int rr = 0; rr < 2; rr++) {
            const int m = mbase + rr * 8;
            if (MODE == 0) {
                const int b = m >> 10, s = m & 1023;
                const bool pad = (kpm[b * 1024 + s] != 0u);
#pragma unroll
                for (int ni = 0; ni < 8; ni++) {
                    const int c = n0 + wn * 64 + ni * 8 + cc * 2;
                    const float v0 = pad ? 0.0f : (acc[mi][ni][rr * 2]     + bias[c]);
                    const float v1 = pad ? 0.0f : (acc[mi][ni][rr * 2 + 1] + bias[c + 1]);
                    const int which = c >> 10;
                    const int e = c & 1023;
                    const int hh = e >> 6, d = e & 63;
                    __half h0 = __float2half_rn(v0), h1 = __float2half_rn(v1);
                    if (which == 0) {
                        const size_t idx = ((size_t)(b * HH + hh) * SS + s) * DKK + d;
                        __half l0 = __float2half_rn(v0 - __half2float(h0));
                        __half l1 = __float2half_rn(v1 - __half2float(h1));
                        *(__half2*)&g_qh[idx] = __halves2half2(h0, h1);
                        *(__half2*)&g_ql[idx] = __halves2half2(l0, l1);
                    } else if (which == 1) {
                        const size_t idx = (size_t)PER
                                         + ((size_t)(b * HH + hh) * SS + s) * DKK + d;
                        *(__half2*)&g_qh[idx] = __halves2half2(h0, h1);
                    } else {
                        __half* vt = g_vt + (size_t)(b * HH + hh) * DKK * SS;
                        vt[(size_t)d * SS + s]       = h0;
                        vt[(size_t)(d + 1) * SS + s] = h1;
                    }
                }
            } else {
#pragma unroll
                for (int ni = 0; ni < 8; ni++) {
                    const int n = n0 + wn * 64 + ni * 8 + cc * 2;
                    out[(size_t)m * 1024 + n]     = acc[mi][ni][rr * 2]     + bias[n];
                    out[(size_t)m * 1024 + n + 1] = acc[mi][ni][rr * 2 + 1] + bias[n + 1];
                }
            }
        }
    }
}

// ---------------------------------------------------------------------------
// Attention Pass A: STATS ONLY. Flat 512-CTA grid, big q-blocks first.
// Skips causal-masked AND fully-padded key tiles.
// ---------------------------------------------------------------------------
#define QS 36

__global__ __launch_bounds__(256) void attn_score_kernel(
    const unsigned int* __restrict__ kpm)
{
    extern __shared__ unsigned sm[];
    unsigned* sQh = sm;
    unsigned* sQl = sQh + 128 * QS;
    unsigned* sKh = sQl + 128 * QS;
    unsigned* sKp = sKh + 128 * QS;

    // big-work-first decode: qblk 7..0 as blockIdx.x grows by 64
    const int qblk = 7 - (blockIdx.x >> 6);
    const int rem  = blockIdx.x & 63;
    const int h = rem & 15, b = rem >> 4;
    const int q0 = qblk * 128;

    const int tid = threadIdx.x, lane = tid & 31, w = tid >> 5;
    const int r = lane >> 2, cc = lane & 3;
    const int lrow16 = lane & 15;
    const int lkoff4 = (lane >> 4) * 4;

    const unsigned sKh_u = (unsigned)__cvta_generic_to_shared(sKh);

    const unsigned* qhw = (const unsigned*)g_qh;
    const unsigned* qlw = (const unsigned*)g_ql;
    const size_t qbase = ((size_t)(b * HH + h) * SS + q0) * 32;
    const size_t kbase = (size_t)PER / 2 + ((size_t)(b * HH + h) * SS) * 32;

    for (int i = tid; i < 1024; i += 256) {
        const int row = i >> 3, off = (i & 7) * 4;
        *(uint4*)&sQh[row * QS + off] = *(const uint4*)(qhw + qbase + row * 32 + off);
        *(uint4*)&sQl[row * QS + off] = *(const uint4*)(qlw + qbase + row * 32 + off);
    }
    __syncthreads();

    const int qr = w * 16 + r;
    unsigned aQh[4][4], aQl[4][4];
#pragma unroll
    for (int ks = 0; ks < 4; ks++) {
        const int bw = ks * 8 + cc;
        aQh[ks][0] = sQh[qr * QS + bw];
        aQh[ks][1] = sQh[(qr + 8) * QS + bw];
        aQh[ks][2] = sQh[qr * QS + bw + 4];
        aQh[ks][3] = sQh[(qr + 8) * QS + bw + 4];
        aQl[ks][0] = sQl[qr * QS + bw];
        aQl[ks][1] = sQl[(qr + 8) * QS + bw];
        aQl[ks][2] = sQl[qr * QS + bw + 4];
        aQl[ks][3] = sQl[(qr + 8) * QS + bw + 4];
    }

    const int row0 = q0 + qr, row1 = row0 + 8;

    float m_run[2] = {-1e30f, -1e30f};
    float l_run[2] = {0.0f, 0.0f};

    int ktpad = 8;
#pragma unroll
    for (int t = 7; t >= 0; t--)
        if (kpm[b * 1024 + t * 128] != 0u) ktpad = t;

    const int ntend = min(qblk, ktpad - 1);
    for (int nt = 0; nt <= ntend; nt++) {
        __syncthreads();
        for (int i = tid; i < 1024; i += 256) {
            const int row = i >> 3, off = (i & 7) * 4;
            const size_t g = kbase + (size_t)(nt * 128 + row) * 32 + off;
            *(uint4*)&sKh[row * QS + off] = *(const uint4*)(qhw + g);
        }
        if (tid < 128) sKp[tid] = kpm[b * 1024 + nt * 128 + tid];
        __syncthreads();

        float acc[16][4];
#pragma unroll
        for (int ni = 0; ni < 16; ni++)
#pragma unroll
            for (int c = 0; c < 4; c++) acc[ni][c] = 0.0f;

#pragma unroll
        for (int ks = 0; ks < 4; ks++) {
#pragma unroll
            for (int pp = 0; pp < 4; pp++) {
                const unsigned koffA = (unsigned)
                    (((2 * pp) * 16 + lrow16) * QS + ks * 8 + lkoff4) * 4u;
                const unsigned koffB = (unsigned)
                    (((2 * pp + 1) * 16 + lrow16) * QS + ks * 8 + lkoff4) * 4u;
                unsigned ba[4], bb[4];
                ldsm4(ba, sKh_u + koffA);
                ldsm4(bb, sKh_u + koffB);
                mma_f16(acc[4 * pp],     aQh[ks], ba[0], ba[2]);
                mma_f16(acc[4 * pp + 1], aQh[ks], ba[1], ba[3]);
                mma_f16(acc[4 * pp + 2], aQh[ks], bb[0], bb[2]);
                mma_f16(acc[4 * pp + 3], aQh[ks], bb[1], bb[3]);
                mma_f16(acc[4 * pp],     aQl[ks], ba[0], ba[2]);
                mma_f16(acc[4 * pp + 1], aQl[ks], ba[1], ba[3]);
                mma_f16(acc[4 * pp + 2], aQl[ks], bb[0], bb[2]);
                mma_f16(acc[4 * pp + 3], aQl[ks], bb[1], bb[3]);
            }
        }

#pragma unroll
        for (int ni = 0; ni < 16; ni++) {
            const int colb = ni * 8 + cc * 2;
            const int col = nt * 128 + colb;
#pragma unroll
            for (int e = 0; e < 2; e++) {
                const bool pad = (sKp[colb + e] != 0u);
                float s0 = acc[ni][e] * 0.125f;
                if (col + e > row0) s0 += NEGV;
                if (pad) s0 = NEGV;
                acc[ni][e] = s0;
                float s1 = acc[ni][2 + e] * 0.125f;
                if (col + e > row1) s1 += NEGV;
                if (pad) s1 = NEGV;
                acc[ni][2 + e] = s1;
            }
        }

        float tm0 = -1e30f, tm1 = -1e30f;
#pragma unroll
        for (int ni = 0; ni < 16; ni++) {
            tm0 = fmaxf(tm0, fmaxf(acc[ni][0], acc[ni][1]));
            tm1 = fmaxf(tm1, fmaxf(acc[ni][2], acc[ni][3]));
        }
        tm0 = fmaxf(tm0, __shfl_xor_sync(0xFFFFFFFFu, tm0, 1));
        tm0 = fmaxf(tm0, __shfl_xor_sync(0xFFFFFFFFu, tm0, 2));
        tm1 = fmaxf(tm1, __shfl_xor_sync(0xFFFFFFFFu, tm1, 1));
        tm1 = fmaxf(tm1, __shfl_xor_sync(0xFFFFFFFFu, tm1, 2));
        const float nm0 = fmaxf(m_run[0], tm0);
        const float nm1 = fmaxf(m_run[1], tm1);
        float s0 = 0.0f, s1 = 0.0f;
#pragma unroll
        for (int ni = 0; ni < 16; ni++) {
            s0 += __expf(acc[ni][0] - nm0) + __expf(acc[ni][1] - nm0);
            s1 += __expf(acc[ni][2] - nm1) + __expf(acc[ni][3] - nm1);
        }
        s0 += __shfl_xor_sync(0xFFFFFFFFu, s0, 1);
        s0 += __shfl_xor_sync(0xFFFFFFFFu, s0, 2);
        s1 += __shfl_xor_sync(0xFFFFFFFFu, s1, 1);
        s1 += __shfl_xor_sync(0xFFFFFFFFu, s1, 2);
        l_run[0] = l_run[0] * __expf(m_run[0] - nm0) + s0;
        l_run[1] = l_run[1] * __expf(m_run[1] - nm1) + s1;
        m_run[0] = nm0; m_run[1] = nm1;
    }

    if (cc == 0) {
        const int sb_ = (b * HH + h) * SS;
        g_m[sb_ + row0] = m_run[0];
        g_m[sb_ + row1] = m_run[1];
        g_linv[sb_ + row0] = 1.0f / l_run[0];
        g_linv[sb_ + row1] = 1.0f / l_run[1];
    }
}

// ---------------------------------------------------------------------------
// Attention Pass B: recompute scores, w -> single gmem write, ctx = W @ V.
// Flat 512-CTA grid, big q-blocks first. Skips causal + padded tiles.
// ---------------------------------------------------------------------------
#define WS 68

__global__ __launch_bounds__(256, 2) void attn_av_kernel(
    const unsigned int* __restrict__ kpm, float* __restrict__ wout)
{
    extern __shared__ unsigned sm2[];
    unsigned* bufK = sm2;
    unsigned* bufV = bufK + 128 * QS;
    unsigned* sKp  = bufV + 128 * QS;
    float*    sM   = (float*)(sKp + 128);
    float*    sLi  = sM + 128;

    const int qblk = 7 - (blockIdx.x >> 6);
    const int rem  = blockIdx.x & 63;
    const int h = rem & 15, b = rem >> 4;
    const int q0 = qblk * 128;

    const int tid = threadIdx.x, lane = tid & 31, w = tid >> 5;
    const int r = lane >> 2, cc = lane & 3;
    const int lrow16 = lane & 15;
    const int lkoff4 = (lane >> 4) * 4;

    const unsigned bufK_u = (unsigned)__cvta_generic_to_shared(bufK);
    const unsigned bufV_u = (unsigned)__cvta_generic_to_shared(bufV);

    const unsigned* qhw = (const unsigned*)g_qh;
    const unsigned* qlw = (const unsigned*)g_ql;
    const size_t qbase = ((size_t)(b * HH + h) * SS + q0) * 32;
    const size_t kbase = (size_t)PER / 2 + ((size_t)(b * HH + h) * SS) * 32;
    const __half* vt = g_vt + (size_t)(b * HH + h) * DKK * SS;

    if (tid < 128) {
        const int sb_ = (b * HH + h) * SS + q0;
        sM[tid]  = g_m[sb_ + tid];
        sLi[tid] = g_linv[sb_ + tid];
    }

    for (int i = tid; i < 1024; i += 256) {
        const int row = i >> 3, off = (i & 7) * 4;
        *(uint4*)&bufK[row * QS + off] = *(const uint4*)(qhw + qbase + row * 32 + off);
        *(uint4*)&bufV[row * QS + off] = *(const uint4*)(qlw + qbase + row * 32 + off);
    }
    __syncthreads();

    const int qr = w * 16 + r;
    unsigned aQh[4][4], aQl[4][4];
#pragma unroll
    for (int ks = 0; ks < 4; ks++) {
        const int bw = ks * 8 + cc;
        aQh[ks][0] = bufK[qr * QS + bw];
        aQh[ks][1] = bufK[(qr + 8) * QS + bw];
        aQh[ks][2] = bufK[qr * QS + bw + 4];
        aQh[ks][3] = bufK[(qr + 8) * QS + bw + 4];
        aQl[ks][0] = bufV[qr * QS + bw];
        aQl[ks][1] = bufV[(qr + 8) * QS + bw];
        aQl[ks][2] = bufV[qr * QS + bw + 4];
        aQl[ks][3] = bufV[(qr + 8) * QS + bw + 4];
    }

    const int row0 = q0 + qr, row1 = row0 + 8;
    const float mm0 = sM[qr],     li0 = sLi[qr];
    const float mm1 = sM[qr + 8], li1 = sLi[qr + 8];
    float* wrow0 = wout + ((size_t)(b * HH + h) * SS + row0) * SS;
    float* wrow1 = wout + ((size_t)(b * HH + h) * SS + row1) * SS;

    float accO[8][4];
#pragma unroll
    for (int ni = 0; ni < 8; ni++)
#pragma unroll
        for (int c = 0; c < 4; c++) accO[ni][c] = 0.0f;

    int ktpad = 8;
#pragma unroll
    for (int t = 7; t >= 0; t--)
        if (kpm[b * 1024 + t * 128] != 0u) ktpad = t;

    const int ktend = min(qblk, ktpad - 1);

    for (int kt = 0; kt <= ktend; kt++) {
        __syncthreads();
        for (int i = tid; i < 1024; i += 256) {
            const int row = i >> 3, off = (i & 7) * 4;
            cpa16(bufK_u + (unsigned)(row * QS + off) * 4u,
                  qhw + kbase + (size_t)(kt * 128 + row) * 32 + off);
        }
        for (int c = tid; c < 1024; c += 256) {
            const int d = c >> 4, off = c & 15;
            cpa16(bufV_u + (unsigned)(d * WS + off * 4) * 4u,
                  vt + (size_t)d * SS + kt * 128 + off * 8);
        }
        cpa_commit();
        if (tid < 128) sKp[tid] = kpm[b * 1024 + kt * 128 + tid];
        cpa_wait0();
        __syncthreads();

#pragma unroll
        for (int half = 0; half < 2; half++) {
            float acc[8][4];
#pragma unroll
            for (int ni = 0; ni < 8; ni++)
#pragma unroll
                for (int c = 0; c < 4; c++) acc[ni][c] = 0.0f;

#pragma unroll
            for (int ks = 0; ks < 4; ks++) {
#pragma unroll
                for (int pp = 0; pp < 2; pp++) {
                    const unsigned koffA = (unsigned)
                        (((half * 4 + 2 * pp) * 16 + lrow16) * QS + ks * 8 + lkoff4) * 4u;
                    const unsigned koffB = (unsigned)
                        (((half * 4 + 2 * pp + 1) * 16 + lrow16) * QS + ks * 8 + lkoff4) * 4u;
                    unsigned ba[4], bb[4];
                    ldsm4(ba, bufK_u + koffA);
                    ldsm4(bb, bufK_u + koffB);
                    mma_f16(acc[4 * pp],     aQh[ks], ba[0], ba[2]);
                    mma_f16(acc[4 * pp + 1], aQh[ks], ba[1], ba[3]);
                    mma_f16(acc[4 * pp + 2], aQh[ks], bb[0], bb[2]);
                    mma_f16(acc[4 * pp + 3], aQh[ks], bb[1], bb[3]);
                    mma_f16(acc[4 * pp],     aQl[ks], ba[0], ba[2]);
                    mma_f16(acc[4 * pp + 1], aQl[ks], ba[1], ba[3]);
                    mma_f16(acc[4 * pp + 2], aQl[ks], bb[0], bb[2]);
                    mma_f16(acc[4 * pp + 3], aQl[ks], bb[1], bb[3]);
                }
            }

#pragma unroll
            for (int pi = 0; pi < 4; pi++) {
#pragma unroll
                for (int sub = 0; sub < 2; sub++) {
                    const int nl = 2 * pi + sub;
                    const int colb = (half * 8 + nl) * 8 + cc * 2;
                    const int col = kt * 128 + colb;
#pragma unroll
                    for (int e = 0; e < 2; e++) {
                        const bool pad = (sKp[colb + e] != 0u);
                        float s0 = acc[nl][e] * 0.125f;
                        if (col + e > row0) s0 += NEGV;
                        if (pad) s0 = NEGV;
                        acc[nl][e] = __expf(s0 - mm0) * li0;
                        float s1 = acc[nl][2 + e] * 0.125f;
                        if (col + e > row1) s1 += NEGV;
                        if (pad) s1 = NEGV;
                        acc[nl][2 + e] = __expf(s1 - mm1) * li1;
                    }
                    *(float2*)(wrow0 + col) = make_float2(acc[nl][0], acc[nl][1]);
                    *(float2*)(wrow1 + col) = make_float2(acc[nl][2], acc[nl][3]);
                }
                unsigned ah[4], al[4];
                float rx, ry;
                ah[0] = pack_hi(acc[2 * pi][0],     acc[2 * pi][1],     rx, ry);
                al[0] = pack_lo(rx, ry);
                ah[1] = pack_hi(acc[2 * pi][2],     acc[2 * pi][3],     rx, ry);
                al[1] = pack_lo(rx, ry);
                ah[2] = pack_hi(acc[2 * pi + 1][0], acc[2 * pi + 1][1], rx, ry);
                al[2] = pack_lo(rx, ry);
                ah[3] = pack_hi(acc[2 * pi + 1][2], acc[2 * pi + 1][3], rx, ry);
                al[3] = pack_lo(rx, ry);

                const int ksv = half * 4 + pi;
#pragma unroll
                for (int pp = 0; pp < 2; pp++) {
                    const unsigned voffA = (unsigned)
                        (((2 * pp) * 16 + lrow16) * WS + ksv * 8 + lkoff4) * 4u;
                    const unsigned voffB = (unsigned)
                        (((2 * pp + 1) * 16 + lrow16) * WS + ksv * 8 + lkoff4) * 4u;
                    unsigned ba[4], bb[4];
                    ldsm4(ba, bufV_u + voffA);
                    ldsm4(bb, bufV_u + voffB);
                    mma_f16(accO[4 * pp],     ah, ba[0], ba[2]);
                    mma_f16(accO[4 * pp + 1], ah, ba[1], ba[3]);
                    mma_f16(accO[4 * pp + 2], ah, bb[0], bb[2]);
                    mma_f16(accO[4 * pp + 3], ah, bb[1], bb[3]);
                    mma_f16(accO[4 * pp],     al, ba[0], ba[2]);
                    mma_f16(accO[4 * pp + 1], al, ba[1], ba[3]);
                    mma_f16(accO[4 * pp + 2], al, bb[0], bb[2]);
                    mma_f16(accO[4 * pp + 3], al, bb[1], bb[3]);
                }
            }
        }
    }

    // zero-fill weights for skipped tiles (causal and/or fully padded)
    {
        const float4 z4 = make_float4(0.f, 0.f, 0.f, 0.f);
        float* wbase = wout + ((size_t)(b * HH + h) * SS + q0) * SS;
        for (int kt = ktend + 1; kt < 8; kt++)
            for (int i = tid; i < 4096; i += 256) {
                const int row = i >> 5, c4 = (i & 31) * 4;
                *(float4*)(wbase + (size_t)row * SS + kt * 128 + c4) = z4;
            }
    }

    __half* cth = (__half*)g_cth;
    __half* ctl = (__half*)g_ctl;
    const size_t o0 = ((size_t)(b * SS + q0 + qr)) * EE + h * DKK;
    const size_t o1 = ((size_t)(b * SS + q0 + qr + 8)) * EE + h * DKK;
#pragma unroll
    for (int ni = 0; ni < 8; ni++) {
        const int d0 = ni * 8 + cc * 2;
        __half h0 = __float2half_rn(accO[ni][0]), h1 = __float2half_rn(accO[ni][1]);
        __half l0 = __float2half_rn(accO[ni][0] - __half2float(h0));
        __half l1 = __float2half_rn(accO[ni][1] - __half2float(h1));
        *(__half2*)(cth + o0 + d0) = __halves2half2(h0, h1);
        *(__half2*)(ctl + o0 + d0) = __halves2half2(l0, l1);
        h0 = __float2half_rn(accO[ni][2]); h1 = __float2half_rn(accO[ni][3]);
        l0 = __float2half_rn(accO[ni][2] - __half2float(h0));
        l1 = __float2half_rn(accO[ni][3] - __half2float(h1));
        *(__half2*)(cth + o1 + d0) = __halves2half2(h0, h1);
        *(__half2*)(ctl + o1 + d0) = __halves2half2(l0, l1);
    }
}

// ---------------------------------------------------------------------------
extern "C" void kernel_launch(void* const* d_in, const int* in_sizes, int n_in,
                              void* d_out, int out_size)
{
    const float*        x     = (const float*)d_in[0];
    const unsigned int* kpm   = (const unsigned int*)d_in[2];
    const float*        qkv_w = (const float*)d_in[3];
    const float*        qkv_b = (const float*)d_in[4];
    const float*        out_w = (const float*)d_in[5];
    const float*        out_b = (const float*)d_in[6];

    float* out  = (float*)d_out;
    float* wout = out + (size_t)BB * SS * EE;

    const int gemmSmem  = 2 * 40960;                               // 80 KB
    const int scoreSmem = (3 * 128 * QS + 128) * 4;                // ~54 KB
    const int avSmem    = (2 * 128 * QS + 128 + 256) * 4;          // ~38 KB
    cudaFuncSetAttribute(gemm_f16_kernel<0>,
                         cudaFuncAttributeMaxDynamicSharedMemorySize, gemmSmem);
    cudaFuncSetAttribute(gemm_f16_kernel<1>,
                         cudaFuncAttributeMaxDynamicSharedMemorySize, gemmSmem);
    cudaFuncSetAttribute(attn_score_kernel,
                         cudaFuncAttributeMaxDynamicSharedMemorySize, scoreSmem);
    cudaFuncSetAttribute(attn_av_kernel,
                         cudaFuncAttributeMaxDynamicSharedMemorySize, avSmem);

    // 0) one-time conversions (single launch)
    cvt_all_kernel<<<8192, 256>>>(x, qkv_w, out_w);

    // 1) QKV projection (128x256 tiles) -> Q (hi/lo), K (hi), V^T (hi)
    gemm_f16_kernel<0><<<dim3(12, 32), 512, gemmSmem>>>(qkv_b, kpm, nullptr);

    // 2a) stats only (big q-blocks first)
    attn_score_kernel<<<512, 256, scoreSmem>>>(kpm);

    // 2b) recompute scores + softmax weights (single write) + ctx
    attn_av_kernel<<<512, 256, avSmem>>>(kpm, wout);

    // 3) output projection (128x256 tiles)
    gemm_f16_kernel<1><<<dim3(4, 32), 512, gemmSmem>>>(out_b, nullptr, out);
}